// round 13
// baseline (speedup 1.0000x reference)
#include <cuda_runtime.h>
#include <cuda_bf16.h>
#include <cstdint>
#include <cstddef>

#define NNODES 100000
#define NE     200000
#define DD     300
#define DD2    600
#define M_PAD  100096   // 128 * 782

#define KP1 320
#define NP1 640
#define KP2 640
#define NP2 384

// ---------------- scratch (static device globals; no runtime allocation) ----
__device__ float g_agg[(size_t)M_PAD * DD];
__device__ __nv_bfloat16 g_a1h[(size_t)M_PAD * KP1];
__device__ __nv_bfloat16 g_a1l[(size_t)M_PAD * KP1];
__device__ __nv_bfloat16 g_h1h[(size_t)M_PAD * KP2];
__device__ __nv_bfloat16 g_h1l[(size_t)M_PAD * KP2];
__device__ __nv_bfloat16 g_bt1h[NP1 * KP1], g_bt1l[NP1 * KP1];
__device__ __nv_bfloat16 g_bt2h[NP2 * KP2], g_bt2l[NP2 * KP2];
__device__ float g_combo[18 * DD];
__device__ float g_stats[2 * DD];
__device__ float g_ss[2 * DD];

// ---------------- PTX helpers (baseline ISA only) ----------------------------
__device__ __forceinline__ uint32_t smem_u32(const void* p)
{
    uint32_t a;
    asm("{ .reg .u64 t; cvta.to.shared.u64 t, %1; cvt.u32.u64 %0, t; }" : "=r"(a) : "l"(p));
    return a;
}

__device__ __forceinline__ void ldsm4(uint32_t r[4], uint32_t addr)
{
    asm volatile("ldmatrix.sync.aligned.m8n8.x4.shared.b16 {%0,%1,%2,%3}, [%4];"
                 : "=r"(r[0]), "=r"(r[1]), "=r"(r[2]), "=r"(r[3]) : "r"(addr));
}

__device__ __forceinline__ void mma16816(float c[4], const uint32_t a[4],
                                         uint32_t b0, uint32_t b1)
{
    asm volatile(
        "mma.sync.aligned.m16n8k16.row.col.f32.bf16.bf16.f32 "
        "{%0,%1,%2,%3}, {%4,%5,%6,%7}, {%8,%9}, {%0,%1,%2,%3};"
        : "+f"(c[0]), "+f"(c[1]), "+f"(c[2]), "+f"(c[3])
        : "r"(a[0]), "r"(a[1]), "r"(a[2]), "r"(a[3]), "r"(b0), "r"(b1));
}

__device__ __forceinline__ void cp16(uint32_t dst, const void* src)
{
    asm volatile("cp.async.cg.shared.global [%0], [%1], 16;" :: "r"(dst), "l"(src));
}
#define CP_COMMIT() asm volatile("cp.async.commit_group;" ::: "memory")
#define CP_WAIT0()  asm volatile("cp.async.wait_group 0;" ::: "memory")
#define CP_WAIT1()  asm volatile("cp.async.wait_group 1;" ::: "memory")

__device__ __forceinline__ uint32_t pack2h(__nv_bfloat16 a, __nv_bfloat16 b)
{
    return (uint32_t)__bfloat16_as_ushort(a) | ((uint32_t)__bfloat16_as_ushort(b) << 16);
}

// smem tile: 128 rows x 32 bf16, row stride 80B (16B-aligned, conflict-free ldmatrix)
#define SROW    80
#define TILE_B  10240          // 128 * SROW
#define STAGE_B 40960          // 4 tiles (Ah, Al, Bh, Bl)
#define GEMM_SMEM (2 * STAGE_B)

// ---------------- small init kernels ---------------------------------------
__global__ void combo_init_kernel(const float* __restrict__ w0, const float* __restrict__ b0,
                                  const float* __restrict__ w1, const float* __restrict__ b1)
{
    int b = blockIdx.x;
    if (b < 18) {
        int i0 = b / 3, i1 = b % 3;
        for (int d = threadIdx.x; d < DD; d += blockDim.x)
            g_combo[b * DD + d] = w0[i0 * DD + d] + b0[d] + w1[i1 * DD + d] + b1[d];
    } else {
        for (int d = threadIdx.x; d < 2 * DD; d += blockDim.x)
            g_stats[d] = 0.f;
    }
}

__global__ void zero_agg_kernel()
{
    const size_t n4 = (size_t)M_PAD * DD / 4;
    float4 z = make_float4(0.f, 0.f, 0.f, 0.f);
    float4* p = (float4*)g_agg;
    for (size_t i = (size_t)blockIdx.x * blockDim.x + threadIdx.x; i < n4;
         i += (size_t)gridDim.x * blockDim.x)
        p[i] = z;
}

__global__ void split_w1_kernel(const float* __restrict__ w1)
{
    int idx = blockIdx.x * blockDim.x + threadIdx.x;
    if (idx >= NP1 * KP1) return;
    int n = idx / KP1, k = idx % KP1;
    float v = (n < DD2 && k < DD) ? w1[(size_t)k * DD2 + n] : 0.f;
    __nv_bfloat16 h = __float2bfloat16_rn(v);
    g_bt1h[idx] = h;
    g_bt1l[idx] = __float2bfloat16_rn(v - __bfloat162float(h));
}

__global__ void split_w2_kernel(const float* __restrict__ w2)
{
    int idx = blockIdx.x * blockDim.x + threadIdx.x;
    if (idx >= NP2 * KP2) return;
    int n = idx / KP2, k = idx % KP2;
    float v = (n < DD && k < DD2) ? w2[(size_t)k * DD + n] : 0.f;
    __nv_bfloat16 h = __float2bfloat16_rn(v);
    g_bt2h[idx] = h;
    g_bt2l[idx] = __float2bfloat16_rn(v - __bfloat162float(h));
}

__global__ void split_a_kernel()
{
    size_t idx = (size_t)blockIdx.x * blockDim.x + threadIdx.x;
    const size_t total = (size_t)M_PAD * KP1;
    if (idx >= total) return;
    int k = (int)(idx % KP1);
    size_t row = idx / KP1;
    float v = (k < DD) ? g_agg[row * DD + k] : 0.f;
    __nv_bfloat16 h = __float2bfloat16_rn(v);
    g_a1h[idx] = h;
    g_a1l[idx] = __float2bfloat16_rn(v - __bfloat162float(h));
}

// ---------------- edge scatter ----------------------------------------------
__global__ void scatter_kernel(const float* __restrict__ nf, const int* __restrict__ src,
                               const int* __restrict__ dst, const int* __restrict__ f0,
                               const int* __restrict__ f1)
{
    int e = (blockIdx.x * blockDim.x + threadIdx.x) >> 5;
    int lane = threadIdx.x & 31;
    if (e >= NE) return;
    int s = __ldg(&src[e]);
    int t = __ldg(&dst[e]);
    int c = __ldg(&f0[e]) * 3 + __ldg(&f1[e]);
    const float4* nrow = (const float4*)(nf + (size_t)s * DD);
    const float4* crow = (const float4*)(g_combo + c * DD);
    float* orow = g_agg + (size_t)t * DD;
    for (int j = lane; j < DD / 4; j += 32) {
        float4 a = nrow[j];
        float4 b = crow[j];
        atomicAdd(orow + j * 4 + 0, a.x + b.x);
        atomicAdd(orow + j * 4 + 1, a.y + b.y);
        atomicAdd(orow + j * 4 + 2, a.z + b.z);
        atomicAdd(orow + j * 4 + 3, a.w + b.w);
    }
}

// ---------------- cp.async double-buffered bf16-split GEMM core -------------
// CTA 128x128, 8 warps (4m x 2n), warp tile 32x64, K tiles of 32.
// 3 products: Ah*Bh + Ah*Bl + Al*Bh, fp32 accumulate (HMMA).
// Stage kt loads into buf kt&1 via cp.async; safe because the last readers of
// that buffer (compute iter kt-2) drained at the end-of-iter barrier of kt-2.
#define GEMM_STAGE(Ah_, Al_, Bh_, Bl_, KP_, kt_, b_)                                \
    do {                                                                            \
        _Pragma("unroll") for (int i = 0; i < 2; ++i) {                             \
            int idx = tid + i * 256;                                                \
            int row = idx >> 2, c16 = idx & 3;                                      \
            uint32_t doff = (uint32_t)(row * SROW + c16 * 16);                      \
            size_t gb = (size_t)(kt_) * 64 + c16 * 16;                              \
            uint32_t base = sb + (b_) * STAGE_B;                                    \
            cp16(base + doff,                                                       \
                 (const char*)((Ah_) + (size_t)(mbase + row) * (KP_)) + gb);        \
            cp16(base + TILE_B + doff,                                              \
                 (const char*)((Al_) + (size_t)(mbase + row) * (KP_)) + gb);        \
            cp16(base + 2 * TILE_B + doff,                                          \
                 (const char*)((Bh_) + (size_t)(nbase + row) * (KP_)) + gb);        \
            cp16(base + 3 * TILE_B + doff,                                          \
                 (const char*)((Bl_) + (size_t)(nbase + row) * (KP_)) + gb);        \
        }                                                                           \
        CP_COMMIT();                                                                \
    } while (0)

#define GEMM_MAIN(Ah_, Al_, Bh_, Bl_, KP_)                                          \
    extern __shared__ __align__(16) char dsm[];                                     \
    const int tid = threadIdx.x, wid = tid >> 5, lane = tid & 31;                   \
    const int warp_m = wid & 3, warp_n = wid >> 2;                                  \
    const int nbase = blockIdx.x * 128;                                             \
    const int mbase = blockIdx.y * 128;                                             \
    const uint32_t sb = smem_u32(dsm);                                              \
    constexpr int NKT = (KP_) / 32;                                                 \
    float acc[2][8][4];                                                             \
    _Pragma("unroll") for (int i = 0; i < 2; ++i)                                   \
    _Pragma("unroll") for (int j = 0; j < 8; ++j)                                   \
    _Pragma("unroll") for (int q = 0; q < 4; ++q) acc[i][j][q] = 0.f;               \
    GEMM_STAGE(Ah_, Al_, Bh_, Bl_, KP_, 0, 0);                                      \
    for (int kt = 0; kt < NKT; ++kt) {                                              \
        const int buf = kt & 1;                                                     \
        if (kt + 1 < NKT) {                                                         \
            GEMM_STAGE(Ah_, Al_, Bh_, Bl_, KP_, kt + 1, buf ^ 1);                   \
            CP_WAIT1();                                                             \
        } else {                                                                    \
            CP_WAIT0();                                                             \
        }                                                                           \
        __syncthreads();                                                            \
        const uint32_t uAh = sb + buf * STAGE_B;                                    \
        const uint32_t uAl = uAh + TILE_B;                                          \
        const uint32_t uBh = uAh + 2 * TILE_B;                                      \
        const uint32_t uBl = uAh + 3 * TILE_B;                                      \
        _Pragma("unroll") for (int kk = 0; kk < 2; ++kk) {                          \
            const int kb = kk * 32;                                                 \
            uint32_t ah[2][4], al[2][4];                                            \
            _Pragma("unroll") for (int mi = 0; mi < 2; ++mi) {                      \
                uint32_t ra = (uint32_t)((warp_m * 32 + mi * 16 + (lane & 15)) * SROW \
                                         + kb + ((lane >> 4) << 4));                \
                ldsm4(ah[mi], uAh + ra);                                            \
                ldsm4(al[mi], uAl + ra);                                            \
            }                                                                       \
            _Pragma("unroll") for (int g = 0; g < 4; ++g) {                         \
                uint32_t bh[4], bl[4];                                              \
                uint32_t rb = (uint32_t)((warp_n * 64 + g * 16 + (lane & 7)         \
                                          + ((lane >> 4) << 3)) * SROW              \
                                         + kb + (((lane >> 3) & 1) << 4));          \
                ldsm4(bh, uBh + rb);                                                \
                ldsm4(bl, uBl + rb);                                                \
                _Pragma("unroll") for (int mi = 0; mi < 2; ++mi)                    \
                _Pragma("unroll") for (int h = 0; h < 2; ++h) {                     \
                    mma16816(acc[mi][g * 2 + h], ah[mi], bh[2 * h], bh[2 * h + 1]); \
                    mma16816(acc[mi][g * 2 + h], ah[mi], bl[2 * h], bl[2 * h + 1]); \
                    mma16816(acc[mi][g * 2 + h], al[mi], bh[2 * h], bh[2 * h + 1]); \
                }                                                                   \
            }                                                                       \
        }                                                                           \
        __syncthreads();                                                            \
    }

// GEMM1: + bias, ReLU, output split to bf16 hi/lo (padded cols -> 0)
__global__ void __launch_bounds__(256, 2) gemm1_mma(
    const __nv_bfloat16* __restrict__ Ah, const __nv_bfloat16* __restrict__ Al,
    const __nv_bfloat16* __restrict__ Bh, const __nv_bfloat16* __restrict__ Bl,
    const float* __restrict__ bias,
    __nv_bfloat16* __restrict__ Ch, __nv_bfloat16* __restrict__ Cl)
{
    GEMM_MAIN(Ah, Al, Bh, Bl, KP1)

#pragma unroll
    for (int mi = 0; mi < 2; ++mi) {
        int row0 = mbase + warp_m * 32 + mi * 16 + (lane >> 2);
#pragma unroll
        for (int n8 = 0; n8 < 8; ++n8) {
            int col = nbase + warp_n * 64 + n8 * 8 + 2 * (lane & 3);
#pragma unroll
            for (int rr = 0; rr < 2; ++rr) {
                int row = row0 + rr * 8;
                uint32_t hv = 0, lv = 0;
                if (col < DD2) {
                    float2 bb = *(const float2*)&bias[col];
                    float v0 = fmaxf(acc[mi][n8][2 * rr] + bb.x, 0.f);
                    float v1 = fmaxf(acc[mi][n8][2 * rr + 1] + bb.y, 0.f);
                    __nv_bfloat16 h0 = __float2bfloat16_rn(v0);
                    __nv_bfloat16 h1 = __float2bfloat16_rn(v1);
                    hv = pack2h(h0, h1);
                    lv = pack2h(__float2bfloat16_rn(v0 - __bfloat162float(h0)),
                                __float2bfloat16_rn(v1 - __bfloat162float(h1)));
                }
                *(uint32_t*)(Ch + (size_t)row * NP1 + col) = hv;
                *(uint32_t*)(Cl + (size_t)row * NP1 + col) = lv;
            }
        }
    }
}

// GEMM2: + bias, fp32 out with row/col guards
__global__ void __launch_bounds__(256, 2) gemm2_mma(
    const __nv_bfloat16* __restrict__ Ah, const __nv_bfloat16* __restrict__ Al,
    const __nv_bfloat16* __restrict__ Bh, const __nv_bfloat16* __restrict__ Bl,
    const float* __restrict__ bias, float* __restrict__ C)
{
    GEMM_MAIN(Ah, Al, Bh, Bl, KP2)

#pragma unroll
    for (int mi = 0; mi < 2; ++mi) {
        int row0 = mbase + warp_m * 32 + mi * 16 + (lane >> 2);
#pragma unroll
        for (int n8 = 0; n8 < 8; ++n8) {
            int col = nbase + warp_n * 64 + n8 * 8 + 2 * (lane & 3);
            if (col >= DD) continue;
            float2 bb = *(const float2*)&bias[col];
#pragma unroll
            for (int rr = 0; rr < 2; ++rr) {
                int row = row0 + rr * 8;
                if (row < NNODES) {
                    float2 v;
                    v.x = acc[mi][n8][2 * rr] + bb.x;
                    v.y = acc[mi][n8][2 * rr + 1] + bb.y;
                    *(float2*)(C + (size_t)row * DD + col) = v;
                }
            }
        }
    }
}

// ---------------- BatchNorm --------------------------------------------------
__global__ void colstats_kernel(const float* __restrict__ X)
{
    int c = threadIdx.x;
    int r0 = blockIdx.x * 250;
    int r1 = min(r0 + 250, NNODES);
    float s = 0.f, q = 0.f;
    for (int r = r0; r < r1; ++r) {
        float v = X[(size_t)r * DD + c];
        s += v;
        q = fmaf(v, v, q);
    }
    atomicAdd(&g_stats[c], s);
    atomicAdd(&g_stats[DD + c], q);
}

__global__ void bn_finalize_kernel(const float* __restrict__ gamma, const float* __restrict__ beta)
{
    int c = threadIdx.x;
    float inv_n = 1.f / (float)NNODES;
    float mean = g_stats[c] * inv_n;
    float var  = g_stats[DD + c] * inv_n - mean * mean;
    float sc = gamma[c] * rsqrtf(var + 1e-5f);
    g_ss[c] = sc;
    g_ss[DD + c] = beta[c] - mean * sc;
}

__global__ void bn_apply_kernel(float* __restrict__ X)
{
    const size_t n4 = (size_t)NNODES * (DD / 4);
    float4* p = (float4*)X;
    for (size_t i = (size_t)blockIdx.x * blockDim.x + threadIdx.x; i < n4;
         i += (size_t)gridDim.x * blockDim.x) {
        int c4 = (int)(i % (DD / 4)) * 4;
        float4 sc = *(const float4*)&g_ss[c4];
        float4 sh = *(const float4*)&g_ss[DD + c4];
        float4 x = p[i];
        x.x = fmaf(x.x, sc.x, sh.x);
        x.y = fmaf(x.y, sc.y, sh.y);
        x.z = fmaf(x.z, sc.z, sh.z);
        x.w = fmaf(x.w, sc.w, sh.w);
        p[i] = x;
    }
}

// ---------------- launch -----------------------------------------------------
extern "C" void kernel_launch(void* const* d_in, const int* in_sizes, int n_in,
                              void* d_out, int out_size)
{
    const float* node_feats = (const float*)d_in[0];
    const int*   src        = (const int*)d_in[1];
    const int*   dst        = (const int*)d_in[2];
    const int*   f0         = (const int*)d_in[3];
    const int*   f1         = (const int*)d_in[4];
    const float* emb_w0     = (const float*)d_in[5];
    const float* emb_b0     = (const float*)d_in[6];
    const float* emb_w1     = (const float*)d_in[7];
    const float* emb_b1     = (const float*)d_in[8];
    const float* w1         = (const float*)d_in[9];
    const float* b1         = (const float*)d_in[10];
    const float* w2         = (const float*)d_in[11];
    const float* b2         = (const float*)d_in[12];
    const float* gamma      = (const float*)d_in[13];
    const float* beta       = (const float*)d_in[14];
    float* out = (float*)d_out;

    __nv_bfloat16 *a1h, *a1l, *h1h, *h1l, *bt1h, *bt1l, *bt2h, *bt2l;
    cudaGetSymbolAddress((void**)&a1h, g_a1h);
    cudaGetSymbolAddress((void**)&a1l, g_a1l);
    cudaGetSymbolAddress((void**)&h1h, g_h1h);
    cudaGetSymbolAddress((void**)&h1l, g_h1l);
    cudaGetSymbolAddress((void**)&bt1h, g_bt1h);
    cudaGetSymbolAddress((void**)&bt1l, g_bt1l);
    cudaGetSymbolAddress((void**)&bt2h, g_bt2h);
    cudaGetSymbolAddress((void**)&bt2l, g_bt2l);

    cudaFuncSetAttribute(gemm1_mma, cudaFuncAttributeMaxDynamicSharedMemorySize, GEMM_SMEM);
    cudaFuncSetAttribute(gemm2_mma, cudaFuncAttributeMaxDynamicSharedMemorySize, GEMM_SMEM);

    combo_init_kernel<<<19, 128>>>(emb_w0, emb_b0, emb_w1, emb_b1);
    zero_agg_kernel<<<2048, 256>>>();
    split_w1_kernel<<<(NP1 * KP1 + 255) / 256, 256>>>(w1);
    split_w2_kernel<<<(NP2 * KP2 + 255) / 256, 256>>>(w2);
    scatter_kernel<<<NE * 32 / 256, 256>>>(node_feats, src, dst, f0, f1);

    {
        size_t total = (size_t)M_PAD * KP1;
        split_a_kernel<<<(unsigned)((total + 255) / 256), 256>>>();
    }

    gemm1_mma<<<dim3(NP1 / 128, M_PAD / 128), 256, GEMM_SMEM>>>(a1h, a1l, bt1h, bt1l, b1, h1h, h1l);
    gemm2_mma<<<dim3(NP2 / 128, M_PAD / 128), 256, GEMM_SMEM>>>(h1h, h1l, bt2h, bt2l, b2, out);

    colstats_kernel<<<400, 300>>>(out);
    bn_finalize_kernel<<<1, 300>>>(gamma, beta);
    bn_apply_kernel<<<2048, 256>>>(out);
}

// round 17
// speedup vs baseline: 1.4827x; 1.4827x over previous
#include <cuda_runtime.h>
#include <cuda_bf16.h>
#include <cstdint>
#include <cstddef>

#define NNODES 100000
#define NE     200000
#define DD     300
#define DD2    600
#define M_PAD  100096   // 128 * 782

#define KP1 320
#define NP1 640
#define KP2 640
#define NP2 384

// ---------------- scratch (static device globals; no runtime allocation) ----
__device__ float g_agg[(size_t)M_PAD * DD];
__device__ __nv_bfloat16 g_h1h[(size_t)M_PAD * KP2];
__device__ __nv_bfloat16 g_h1l[(size_t)M_PAD * KP2];
__device__ __nv_bfloat16 g_bt1h[NP1 * KP1], g_bt1l[NP1 * KP1];
__device__ __nv_bfloat16 g_bt2h[NP2 * KP2], g_bt2l[NP2 * KP2];
__device__ float g_combo[18 * DD];
__device__ float g_stats[2 * DD];
__device__ float g_ss[2 * DD];

// ---------------- PTX helpers (baseline ISA only) ----------------------------
__device__ __forceinline__ uint32_t smem_u32(const void* p)
{
    uint32_t a;
    asm("{ .reg .u64 t; cvta.to.shared.u64 t, %1; cvt.u32.u64 %0, t; }" : "=r"(a) : "l"(p));
    return a;
}

__device__ __forceinline__ void ldsm4(uint32_t r[4], uint32_t addr)
{
    asm volatile("ldmatrix.sync.aligned.m8n8.x4.shared.b16 {%0,%1,%2,%3}, [%4];"
                 : "=r"(r[0]), "=r"(r[1]), "=r"(r[2]), "=r"(r[3]) : "r"(addr));
}

__device__ __forceinline__ void mma16816(float c[4], const uint32_t a[4],
                                         uint32_t b0, uint32_t b1)
{
    asm volatile(
        "mma.sync.aligned.m16n8k16.row.col.f32.bf16.bf16.f32 "
        "{%0,%1,%2,%3}, {%4,%5,%6,%7}, {%8,%9}, {%0,%1,%2,%3};"
        : "+f"(c[0]), "+f"(c[1]), "+f"(c[2]), "+f"(c[3])
        : "r"(a[0]), "r"(a[1]), "r"(a[2]), "r"(a[3]), "r"(b0), "r"(b1));
}

__device__ __forceinline__ uint32_t pack2h(__nv_bfloat16 a, __nv_bfloat16 b)
{
    return (uint32_t)__bfloat16_as_ushort(a) | ((uint32_t)__bfloat16_as_ushort(b) << 16);
}

__device__ __forceinline__ void split8(const float f[8], uint32_t hw[4], uint32_t lw[4])
{
#pragma unroll
    for (int j = 0; j < 4; ++j) {
        __nv_bfloat16 h0 = __float2bfloat16_rn(f[2 * j]);
        __nv_bfloat16 h1 = __float2bfloat16_rn(f[2 * j + 1]);
        float l0 = f[2 * j] - __bfloat162float(h0);
        float l1 = f[2 * j + 1] - __bfloat162float(h1);
        hw[j] = pack2h(h0, h1);
        lw[j] = pack2h(__float2bfloat16_rn(l0), __float2bfloat16_rn(l1));
    }
}

// smem tile: 128 rows x 32 bf16, row stride 80 bytes (16B-aligned rows,
// 8-row ldmatrix phases hit 8 distinct bank groups)
#define SROW 80

// ---------------- small init kernels ---------------------------------------
__global__ void combo_init_kernel(const float* __restrict__ w0, const float* __restrict__ b0,
                                  const float* __restrict__ w1, const float* __restrict__ b1)
{
    int b = blockIdx.x;
    if (b < 18) {
        int i0 = b / 3, i1 = b % 3;
        for (int d = threadIdx.x; d < DD; d += blockDim.x)
            g_combo[b * DD + d] = w0[i0 * DD + d] + b0[d] + w1[i1 * DD + d] + b1[d];
    } else {
        for (int d = threadIdx.x; d < 2 * DD; d += blockDim.x)
            g_stats[d] = 0.f;
    }
}

__global__ void zero_agg_kernel()
{
    const size_t n4 = (size_t)M_PAD * DD / 4;
    float4 z = make_float4(0.f, 0.f, 0.f, 0.f);
    float4* p = (float4*)g_agg;
    for (size_t i = (size_t)blockIdx.x * blockDim.x + threadIdx.x; i < n4;
         i += (size_t)gridDim.x * blockDim.x)
        p[i] = z;
}

__global__ void split_w1_kernel(const float* __restrict__ w1)
{
    int idx = blockIdx.x * blockDim.x + threadIdx.x;
    if (idx >= NP1 * KP1) return;
    int n = idx / KP1, k = idx % KP1;
    float v = (n < DD2 && k < DD) ? w1[(size_t)k * DD2 + n] : 0.f;
    __nv_bfloat16 h = __float2bfloat16_rn(v);
    g_bt1h[idx] = h;
    g_bt1l[idx] = __float2bfloat16_rn(v - __bfloat162float(h));
}

__global__ void split_w2_kernel(const float* __restrict__ w2)
{
    int idx = blockIdx.x * blockDim.x + threadIdx.x;
    if (idx >= NP2 * KP2) return;
    int n = idx / KP2, k = idx % KP2;
    float v = (n < DD && k < DD2) ? w2[(size_t)k * DD + n] : 0.f;
    __nv_bfloat16 h = __float2bfloat16_rn(v);
    g_bt2h[idx] = h;
    g_bt2l[idx] = __float2bfloat16_rn(v - __bfloat162float(h));
}

// ---------------- edge scatter (scalar atomics — proven) ---------------------
__global__ void scatter_kernel(const float* __restrict__ nf, const int* __restrict__ src,
                               const int* __restrict__ dst, const int* __restrict__ f0,
                               const int* __restrict__ f1)
{
    int e = (blockIdx.x * blockDim.x + threadIdx.x) >> 5;
    int lane = threadIdx.x & 31;
    if (e >= NE) return;
    int s = __ldg(&src[e]);
    int t = __ldg(&dst[e]);
    int c = __ldg(&f0[e]) * 3 + __ldg(&f1[e]);
    const float4* nrow = (const float4*)(nf + (size_t)s * DD);
    const float4* crow = (const float4*)(g_combo + c * DD);
    float* orow = g_agg + (size_t)t * DD;
    for (int j = lane; j < DD / 4; j += 32) {
        float4 a = nrow[j];
        float4 b = crow[j];
        atomicAdd(orow + j * 4 + 0, a.x + b.x);
        atomicAdd(orow + j * 4 + 1, a.y + b.y);
        atomicAdd(orow + j * 4 + 2, a.z + b.z);
        atomicAdd(orow + j * 4 + 3, a.w + b.w);
    }
}

// ---------------- mma.sync bf16-split GEMM compute phase (R12 proven) --------
#define GEMM_PROLOG()                                                               \
    __shared__ __align__(16) char sAh[128 * SROW], sAl[128 * SROW];                 \
    __shared__ __align__(16) char sBh[128 * SROW], sBl[128 * SROW];                 \
    const int tid = threadIdx.x, wid = tid >> 5, lane = tid & 31;                   \
    const int warp_m = wid & 3, warp_n = wid >> 2;                                  \
    const int nbase = blockIdx.x * 128;                                             \
    const int mbase = blockIdx.y * 128;                                             \
    const uint32_t uAh = smem_u32(sAh), uAl = smem_u32(sAl);                        \
    const uint32_t uBh = smem_u32(sBh), uBl = smem_u32(sBl);                        \
    float acc[2][8][4];                                                             \
    _Pragma("unroll") for (int i = 0; i < 2; ++i)                                   \
    _Pragma("unroll") for (int j = 0; j < 8; ++j)                                   \
    _Pragma("unroll") for (int q = 0; q < 4; ++q) acc[i][j][q] = 0.f;

#define GEMM_COMPUTE_TILE()                                                         \
    do {                                                                            \
        _Pragma("unroll") for (int kk = 0; kk < 2; ++kk) {                          \
            const int kb = kk * 32;                                                 \
            uint32_t ah[2][4], al[2][4];                                            \
            _Pragma("unroll") for (int mi = 0; mi < 2; ++mi) {                      \
                uint32_t ra = (uint32_t)((warp_m * 32 + mi * 16 + (lane & 15)) * SROW \
                                         + kb + ((lane >> 4) << 4));                \
                ldsm4(ah[mi], uAh + ra);                                            \
                ldsm4(al[mi], uAl + ra);                                            \
            }                                                                       \
            _Pragma("unroll") for (int g = 0; g < 4; ++g) {                         \
                uint32_t bh[4], bl[4];                                              \
                uint32_t rb = (uint32_t)((warp_n * 64 + g * 16 + (lane & 7)         \
                                          + ((lane >> 4) << 3)) * SROW              \
                                         + kb + (((lane >> 3) & 1) << 4));          \
                ldsm4(bh, uBh + rb);                                                \
                ldsm4(bl, uBl + rb);                                                \
                _Pragma("unroll") for (int mi = 0; mi < 2; ++mi)                    \
                _Pragma("unroll") for (int h = 0; h < 2; ++h) {                     \
                    mma16816(acc[mi][g * 2 + h], ah[mi], bh[2 * h], bh[2 * h + 1]); \
                    mma16816(acc[mi][g * 2 + h], ah[mi], bl[2 * h], bl[2 * h + 1]); \
                    mma16816(acc[mi][g * 2 + h], al[mi], bh[2 * h], bh[2 * h + 1]); \
                }                                                                   \
            }                                                                       \
        }                                                                           \
    } while (0)

// GEMM1: A is fp32 (g_agg), split to bf16 hi/lo in-register during staging.
// B pre-split. Epilogue: + bias, ReLU, output split to bf16 hi/lo.
__global__ void __launch_bounds__(256, 2) gemm1_mma(
    const float* __restrict__ Afp,
    const __nv_bfloat16* __restrict__ Bh, const __nv_bfloat16* __restrict__ Bl,
    const float* __restrict__ bias,
    __nv_bfloat16* __restrict__ Ch, __nv_bfloat16* __restrict__ Cl)
{
    GEMM_PROLOG()

    for (int kt = 0; kt < KP1 / 32; ++kt) {
#pragma unroll
        for (int i = 0; i < 2; ++i) {
            int idx = tid + i * 256;
            int row = idx >> 2, c4 = idx & 3;
            // ---- A: fp32 load + hi/lo split (8 floats -> 16B hi + 16B lo) ----
            int k0 = kt * 32 + c4 * 8;
            const float* ap = Afp + (size_t)(mbase + row) * DD + k0;
            float f[8];
            if (k0 + 8 <= DD) {
                float4 v0 = *(const float4*)ap;
                float4 v1 = *(const float4*)(ap + 4);
                f[0] = v0.x; f[1] = v0.y; f[2] = v0.z; f[3] = v0.w;
                f[4] = v1.x; f[5] = v1.y; f[6] = v1.z; f[7] = v1.w;
            } else {
#pragma unroll
                for (int j = 0; j < 8; ++j)
                    f[j] = (k0 + j < DD) ? ap[j] : 0.f;
            }
            uint32_t hw[4], lw[4];
            split8(f, hw, lw);
            uint32_t doff = (uint32_t)(row * SROW + c4 * 16);
            *(uint4*)(sAh + doff) = make_uint4(hw[0], hw[1], hw[2], hw[3]);
            *(uint4*)(sAl + doff) = make_uint4(lw[0], lw[1], lw[2], lw[3]);
            // ---- B: pre-split bf16 ----
            const uint4* pb_h = (const uint4*)(Bh + (size_t)(nbase + row) * KP1) + kt * 4 + c4;
            const uint4* pb_l = (const uint4*)(Bl + (size_t)(nbase + row) * KP1) + kt * 4 + c4;
            *(uint4*)(sBh + doff) = *pb_h;
            *(uint4*)(sBl + doff) = *pb_l;
        }
        __syncthreads();
        GEMM_COMPUTE_TILE();
        __syncthreads();
    }

#pragma unroll
    for (int mi = 0; mi < 2; ++mi) {
        int row0 = mbase + warp_m * 32 + mi * 16 + (lane >> 2);
#pragma unroll
        for (int n8 = 0; n8 < 8; ++n8) {
            int col = nbase + warp_n * 64 + n8 * 8 + 2 * (lane & 3);
#pragma unroll
            for (int rr = 0; rr < 2; ++rr) {
                int row = row0 + rr * 8;
                uint32_t hv = 0, lv = 0;
                if (col < DD2) {
                    float2 bb = *(const float2*)&bias[col];
                    float v0 = fmaxf(acc[mi][n8][2 * rr] + bb.x, 0.f);
                    float v1 = fmaxf(acc[mi][n8][2 * rr + 1] + bb.y, 0.f);
                    __nv_bfloat16 h0 = __float2bfloat16_rn(v0);
                    __nv_bfloat16 h1 = __float2bfloat16_rn(v1);
                    hv = pack2h(h0, h1);
                    lv = pack2h(__float2bfloat16_rn(v0 - __bfloat162float(h0)),
                                __float2bfloat16_rn(v1 - __bfloat162float(h1)));
                }
                *(uint32_t*)(Ch + (size_t)row * NP1 + col) = hv;
                *(uint32_t*)(Cl + (size_t)row * NP1 + col) = lv;
            }
        }
    }
}

// GEMM2: both operands pre-split bf16; + bias, fp32 out with guards
__global__ void __launch_bounds__(256, 2) gemm2_mma(
    const __nv_bfloat16* __restrict__ Ah, const __nv_bfloat16* __restrict__ Al,
    const __nv_bfloat16* __restrict__ Bh, const __nv_bfloat16* __restrict__ Bl,
    const float* __restrict__ bias, float* __restrict__ C)
{
    GEMM_PROLOG()

    for (int kt = 0; kt < KP2 / 32; ++kt) {
#pragma unroll
        for (int i = 0; i < 2; ++i) {
            int idx = tid + i * 256;
            int row = idx >> 2, c4 = idx & 3;
            uint32_t doff = (uint32_t)(row * SROW + c4 * 16);
            const uint4* pa_h = (const uint4*)(Ah + (size_t)(mbase + row) * KP2) + kt * 4 + c4;
            const uint4* pa_l = (const uint4*)(Al + (size_t)(mbase + row) * KP2) + kt * 4 + c4;
            const uint4* pb_h = (const uint4*)(Bh + (size_t)(nbase + row) * KP2) + kt * 4 + c4;
            const uint4* pb_l = (const uint4*)(Bl + (size_t)(nbase + row) * KP2) + kt * 4 + c4;
            *(uint4*)(sAh + doff) = *pa_h;
            *(uint4*)(sAl + doff) = *pa_l;
            *(uint4*)(sBh + doff) = *pb_h;
            *(uint4*)(sBl + doff) = *pb_l;
        }
        __syncthreads();
        GEMM_COMPUTE_TILE();
        __syncthreads();
    }

#pragma unroll
    for (int mi = 0; mi < 2; ++mi) {
        int row0 = mbase + warp_m * 32 + mi * 16 + (lane >> 2);
#pragma unroll
        for (int n8 = 0; n8 < 8; ++n8) {
            int col = nbase + warp_n * 64 + n8 * 8 + 2 * (lane & 3);
            if (col >= DD) continue;
            float2 bb = *(const float2*)&bias[col];
#pragma unroll
            for (int rr = 0; rr < 2; ++rr) {
                int row = row0 + rr * 8;
                if (row < NNODES) {
                    float2 v;
                    v.x = acc[mi][n8][2 * rr] + bb.x;
                    v.y = acc[mi][n8][2 * rr + 1] + bb.y;
                    *(float2*)(C + (size_t)row * DD + col) = v;
                }
            }
        }
    }
}

// ---------------- BatchNorm --------------------------------------------------
__global__ void colstats_kernel(const float* __restrict__ X)
{
    int c = threadIdx.x;
    int r0 = blockIdx.x * 250;
    int r1 = min(r0 + 250, NNODES);
    float s = 0.f, q = 0.f;
    for (int r = r0; r < r1; ++r) {
        float v = X[(size_t)r * DD + c];
        s += v;
        q = fmaf(v, v, q);
    }
    atomicAdd(&g_stats[c], s);
    atomicAdd(&g_stats[DD + c], q);
}

__global__ void bn_finalize_kernel(const float* __restrict__ gamma, const float* __restrict__ beta)
{
    int c = threadIdx.x;
    float inv_n = 1.f / (float)NNODES;
    float mean = g_stats[c] * inv_n;
    float var  = g_stats[DD + c] * inv_n - mean * mean;
    float sc = gamma[c] * rsqrtf(var + 1e-5f);
    g_ss[c] = sc;
    g_ss[DD + c] = beta[c] - mean * sc;
}

__global__ void bn_apply_kernel(float* __restrict__ X)
{
    const size_t n4 = (size_t)NNODES * (DD / 4);
    float4* p = (float4*)X;
    for (size_t i = (size_t)blockIdx.x * blockDim.x + threadIdx.x; i < n4;
         i += (size_t)gridDim.x * blockDim.x) {
        int c4 = (int)(i % (DD / 4)) * 4;
        float4 sc = *(const float4*)&g_ss[c4];
        float4 sh = *(const float4*)&g_ss[DD + c4];
        float4 x = p[i];
        x.x = fmaf(x.x, sc.x, sh.x);
        x.y = fmaf(x.y, sc.y, sh.y);
        x.z = fmaf(x.z, sc.z, sh.z);
        x.w = fmaf(x.w, sc.w, sh.w);
        p[i] = x;
    }
}

// ---------------- launch -----------------------------------------------------
extern "C" void kernel_launch(void* const* d_in, const int* in_sizes, int n_in,
                              void* d_out, int out_size)
{
    const float* node_feats = (const float*)d_in[0];
    const int*   src        = (const int*)d_in[1];
    const int*   dst        = (const int*)d_in[2];
    const int*   f0         = (const int*)d_in[3];
    const int*   f1         = (const int*)d_in[4];
    const float* emb_w0     = (const float*)d_in[5];
    const float* emb_b0     = (const float*)d_in[6];
    const float* emb_w1     = (const float*)d_in[7];
    const float* emb_b1     = (const float*)d_in[8];
    const float* w1         = (const float*)d_in[9];
    const float* b1         = (const float*)d_in[10];
    const float* w2         = (const float*)d_in[11];
    const float* b2         = (const float*)d_in[12];
    const float* gamma      = (const float*)d_in[13];
    const float* beta       = (const float*)d_in[14];
    float* out = (float*)d_out;

    float* agg; cudaGetSymbolAddress((void**)&agg, g_agg);
    __nv_bfloat16 *h1h, *h1l, *bt1h, *bt1l, *bt2h, *bt2l;
    cudaGetSymbolAddress((void**)&h1h, g_h1h);
    cudaGetSymbolAddress((void**)&h1l, g_h1l);
    cudaGetSymbolAddress((void**)&bt1h, g_bt1h);
    cudaGetSymbolAddress((void**)&bt1l, g_bt1l);
    cudaGetSymbolAddress((void**)&bt2h, g_bt2h);
    cudaGetSymbolAddress((void**)&bt2l, g_bt2l);

    combo_init_kernel<<<19, 128>>>(emb_w0, emb_b0, emb_w1, emb_b1);
    zero_agg_kernel<<<2048, 256>>>();
    split_w1_kernel<<<(NP1 * KP1 + 255) / 256, 256>>>(w1);
    split_w2_kernel<<<(NP2 * KP2 + 255) / 256, 256>>>(w2);
    scatter_kernel<<<NE * 32 / 256, 256>>>(node_feats, src, dst, f0, f1);

    gemm1_mma<<<dim3(NP1 / 128, M_PAD / 128), 256>>>(agg, bt1h, bt1l, b1, h1h, h1l);
    gemm2_mma<<<dim3(NP2 / 128, M_PAD / 128), 256>>>(h1h, h1l, bt2h, bt2l, b2, out);

    colstats_kernel<<<400, 300>>>(out);
    bn_finalize_kernel<<<1, 300>>>(gamma, beta);
    bn_apply_kernel<<<2048, 256>>>(out);
}